// round 6
// baseline (speedup 1.0000x reference)
#include <cuda_runtime.h>
#include <cuda_bf16.h>
#include <math.h>
#include <stdint.h>

// Problem constants (fixed shapes from reference)
#define NQ    16384
#define NK    7933
#define NK_PAD 7936
#define D_IN  1024
#define HD    512
#define THRE_IDX 11469   // NQ - int(0.3*NQ)

// ---------------------------------------------------------------------------
// Scratch (device globals)
// ---------------------------------------------------------------------------
__device__ __align__(16) float g_qt[NQ * HD];   // tanh(query @ wq^T)
__device__ __align__(16) float g_kt[NK * HD];   // tanh(key_x @ wk^T)
__device__ float g_qn2[NQ];
__device__ float g_kn2[NK];
__device__ __align__(16) float g_v[HD];
__device__ float g_A1[NQ];
__device__ float g_thre;
__device__ float g_m;
__device__ float g_Z;
__device__ float g_z[HD];

// pre-converted bf16 hi/lo operands
__device__ __align__(16) __nv_bfloat16 g_qh[NQ * D_IN];
__device__ __align__(16) __nv_bfloat16 g_ql[NQ * D_IN];
__device__ __align__(16) __nv_bfloat16 g_kh[NK_PAD * D_IN];
__device__ __align__(16) __nv_bfloat16 g_kl[NK_PAD * D_IN];
__device__ __align__(16) __nv_bfloat16 g_wqh[HD * D_IN];
__device__ __align__(16) __nv_bfloat16 g_wql[HD * D_IN];
__device__ __align__(16) __nv_bfloat16 g_wkh[HD * D_IN];
__device__ __align__(16) __nv_bfloat16 g_wkl[HD * D_IN];

// ---------------------------------------------------------------------------
__global__ void init_kernel() {
    int i = blockIdx.x * 256 + threadIdx.x;
    if (i < NQ) g_qn2[i] = 0.f;
    if (i < NK) g_kn2[i] = 0.f;
    if (i < HD) { g_v[i] = 0.f; g_z[i] = 0.f; }
    if (i == 0) g_Z = 0.f;
}

// ---------------------------------------------------------------------------
// Streaming fp32 -> bf16 hi/lo split of all GEMM operands.
// ---------------------------------------------------------------------------
#define Q4   (NQ * 256)        // float4 granules in query
#define K4   (NK_PAD * 256)
#define KS4  (NK * 256)
#define W4   (HD * 256)
#define TOT4 (Q4 + K4 + 2 * W4)

__device__ __forceinline__ void split4(float4 v, uint2& h, uint2& l) {
    __nv_bfloat162 h01 = __floats2bfloat162_rn(v.x, v.y);
    __nv_bfloat162 h23 = __floats2bfloat162_rn(v.z, v.w);
    __nv_bfloat162 l01 = __floats2bfloat162_rn(v.x - __bfloat162float(h01.x),
                                               v.y - __bfloat162float(h01.y));
    __nv_bfloat162 l23 = __floats2bfloat162_rn(v.z - __bfloat162float(h23.x),
                                               v.w - __bfloat162float(h23.y));
    h = make_uint2(*(uint32_t*)&h01, *(uint32_t*)&h23);
    l = make_uint2(*(uint32_t*)&l01, *(uint32_t*)&l23);
}

__global__ __launch_bounds__(256)
void convert_kernel(const float* __restrict__ query, const float* __restrict__ key_x,
                    const float* __restrict__ wq_w, const float* __restrict__ wk_w) {
    int stride = gridDim.x * 256;
    for (int gi = blockIdx.x * 256 + threadIdx.x; gi < TOT4; gi += stride) {
        uint2 h = make_uint2(0u, 0u), l = make_uint2(0u, 0u);
        uint2 *hp, *lp; int idx;
        if (gi < Q4) {
            idx = gi;
            split4(((const float4*)query)[idx], h, l);
            hp = (uint2*)g_qh; lp = (uint2*)g_ql;
        } else if (gi < Q4 + K4) {
            idx = gi - Q4;
            if (idx < KS4) split4(((const float4*)key_x)[idx], h, l);
            hp = (uint2*)g_kh; lp = (uint2*)g_kl;
        } else if (gi < Q4 + K4 + W4) {
            idx = gi - Q4 - K4;
            split4(((const float4*)wq_w)[idx], h, l);
            hp = (uint2*)g_wqh; lp = (uint2*)g_wql;
        } else {
            idx = gi - Q4 - K4 - W4;
            split4(((const float4*)wk_w)[idx], h, l);
            hp = (uint2*)g_wkh; lp = (uint2*)g_wkl;
        }
        hp[idx] = h;
        lp[idx] = l;
    }
}

// ---------------------------------------------------------------------------
// mma.sync bf16 GEMM + tanh + fused row-norm accumulation.
// Operands pre-split in gmem; mainloop = cp.async + ldmatrix + HMMA only.
// Block 128x128, 8 warps, K-chunk 32, 2-stage cp.async pipeline, 2 CTA/SM.
// ---------------------------------------------------------------------------
__device__ __forceinline__ uint32_t smem_u32(const void* p) {
    uint32_t a;
    asm("{ .reg .u64 t; cvta.to.shared.u64 t, %1; cvt.u32.u64 %0, t; }" : "=r"(a) : "l"(p));
    return a;
}
__device__ __forceinline__ void ldm_x4(uint32_t* r, uint32_t addr) {
    asm volatile("ldmatrix.sync.aligned.m8n8.x4.shared.b16 {%0,%1,%2,%3}, [%4];"
                 : "=r"(r[0]), "=r"(r[1]), "=r"(r[2]), "=r"(r[3]) : "r"(addr));
}
__device__ __forceinline__ void mma_bf16(float* d, const uint32_t* a, const uint32_t* b) {
    asm volatile(
        "mma.sync.aligned.m16n8k16.row.col.f32.bf16.bf16.f32 "
        "{%0,%1,%2,%3}, {%4,%5,%6,%7}, {%8,%9}, {%0,%1,%2,%3};"
        : "+f"(d[0]), "+f"(d[1]), "+f"(d[2]), "+f"(d[3])
        : "r"(a[0]), "r"(a[1]), "r"(a[2]), "r"(a[3]), "r"(b[0]), "r"(b[1]));
}
__device__ __forceinline__ void cp16(uint32_t s, const void* g) {
    asm volatile("cp.async.cg.shared.global [%0], [%1], 16;" :: "r"(s), "l"(g));
}

#define LDS 40                     // bf16 row stride (32 + 8 pad) = 80B
#define TILE_B 10240               // 128 * 80
#define STAGE_B 40960              // 4 tiles
#define NCH2 (D_IN / 32)           // 32 chunks
#define GEMM_SMEM (2 * STAGE_B)    // 81920

__device__ __forceinline__ void issue_chunk(
    uint32_t sstage,
    const __nv_bfloat16* __restrict__ Ah, const __nv_bfloat16* __restrict__ Al,
    const __nv_bfloat16* __restrict__ Wh, const __nv_bfloat16* __restrict__ Wl,
    int bm, int bn, int k0, int tid)
{
#pragma unroll
    for (int t = 0; t < 4; t++) {
        const __nv_bfloat16* src = (t == 0) ? Ah : (t == 1) ? Al : (t == 2) ? Wh : Wl;
        const int row0 = (t < 2) ? bm : bn;
        const uint32_t sbase = sstage + t * TILE_B;
#pragma unroll
        for (int j = 0; j < 2; j++) {
            int id = tid + j * 256;        // 0..511
            int r = id >> 2, c8 = id & 3;
            cp16(sbase + r * 80 + c8 * 16,
                 src + (size_t)(row0 + r) * D_IN + k0 + c8 * 8);
        }
    }
}

__global__ __launch_bounds__(256, 2)
void gemm_tc_kernel(const float* __restrict__ wq_b, const float* __restrict__ wk_b)
{
    extern __shared__ __align__(16) char sm[];
    const int tid = threadIdx.x;
    const int wid = tid >> 5;
    const int lane = tid & 31;
    const int by = blockIdx.y;

    const __nv_bfloat16 *Ah, *Al, *Wh, *Wl;
    const float* bias; float* C; float* N2; int M, bm;
    if (by < 128) {
        Ah = g_qh; Al = g_ql; Wh = g_wqh; Wl = g_wql;
        bias = wq_b; C = g_qt; N2 = g_qn2; M = NQ; bm = by * 128;
    } else {
        Ah = g_kh; Al = g_kl; Wh = g_wkh; Wl = g_wkl;
        bias = wk_b; C = g_kt; N2 = g_kn2; M = NK; bm = (by - 128) * 128;
    }
    const int bn = blockIdx.x * 128;

    const uint32_t smb = smem_u32(sm);
    const int warp_m = (wid & 3) * 32;
    const int warp_n = (wid >> 2) * 64;

    float acc[2][8][4];
#pragma unroll
    for (int mt = 0; mt < 2; mt++)
#pragma unroll
        for (int nt = 0; nt < 8; nt++)
#pragma unroll
            for (int i = 0; i < 4; i++) acc[mt][nt][i] = 0.f;

    issue_chunk(smb, Ah, Al, Wh, Wl, bm, bn, 0, tid);
    asm volatile("cp.async.commit_group;");

    for (int c = 0; c < NCH2; c++) {
        if (c + 1 < NCH2) {
            issue_chunk(smb + ((c + 1) & 1) * STAGE_B, Ah, Al, Wh, Wl,
                        bm, bn, (c + 1) * 32, tid);
            asm volatile("cp.async.commit_group;");
            asm volatile("cp.async.wait_group 1;");
        } else {
            asm volatile("cp.async.wait_group 0;");
        }
        __syncthreads();

        const uint32_t st = smb + (c & 1) * STAGE_B;
#pragma unroll
        for (int kk = 0; kk < 2; kk++) {
            uint32_t ah[2][4], al[2][4];
#pragma unroll
            for (int mt = 0; mt < 2; mt++) {
                int r = warp_m + mt * 16 + (lane & 15);
                int cc = kk * 16 + (lane >> 4) * 8;
                uint32_t off = (uint32_t)(r * LDS + cc) * 2;
                ldm_x4(ah[mt], st + off);
                ldm_x4(al[mt], st + TILE_B + off);
            }
#pragma unroll
            for (int nt2 = 0; nt2 < 4; nt2++) {
                uint32_t bh[4], bl[4];
                int r = warp_n + nt2 * 16 + ((lane >> 4) ? 8 : 0) + (lane & 7);
                int cc = kk * 16 + ((lane >> 3) & 1) * 8;
                uint32_t off = (uint32_t)(r * LDS + cc) * 2;
                ldm_x4(bh, st + 2 * TILE_B + off);
                ldm_x4(bl, st + 3 * TILE_B + off);
#pragma unroll
                for (int mt = 0; mt < 2; mt++)
#pragma unroll
                    for (int hf = 0; hf < 2; hf++) {
                        int nt = nt2 * 2 + hf;
                        mma_bf16(acc[mt][nt], ah[mt], &bh[hf * 2]);
                        mma_bf16(acc[mt][nt], ah[mt], &bl[hf * 2]);
                        mma_bf16(acc[mt][nt], al[mt], &bh[hf * 2]);
                    }
            }
        }
        __syncthreads();
    }

    // ---- epilogue: bias + tanh + fused row-norm partials ----
    float rs[2][2] = {{0.f, 0.f}, {0.f, 0.f}};
#pragma unroll
    for (int mt = 0; mt < 2; mt++) {
        int r0 = bm + warp_m + mt * 16 + (lane >> 2);
#pragma unroll
        for (int nt = 0; nt < 8; nt++) {
            int gc = bn + warp_n + nt * 8 + (lane & 3) * 2;
            float b0 = bias[gc], b1 = bias[gc + 1];
            if (r0 < M) {
                float t0 = tanhf(acc[mt][nt][0] + b0);
                float t1 = tanhf(acc[mt][nt][1] + b1);
                C[(size_t)r0 * HD + gc]     = t0;
                C[(size_t)r0 * HD + gc + 1] = t1;
                rs[mt][0] = fmaf(t0, t0, fmaf(t1, t1, rs[mt][0]));
            }
            if (r0 + 8 < M) {
                float t2 = tanhf(acc[mt][nt][2] + b0);
                float t3 = tanhf(acc[mt][nt][3] + b1);
                C[(size_t)(r0 + 8) * HD + gc]     = t2;
                C[(size_t)(r0 + 8) * HD + gc + 1] = t3;
                rs[mt][1] = fmaf(t2, t2, fmaf(t3, t3, rs[mt][1]));
            }
        }
    }
#pragma unroll
    for (int mt = 0; mt < 2; mt++)
#pragma unroll
        for (int h = 0; h < 2; h++) {
            float v = rs[mt][h];
            v += __shfl_xor_sync(0xffffffffu, v, 1);
            v += __shfl_xor_sync(0xffffffffu, v, 2);
            int row = bm + warp_m + mt * 16 + (lane >> 2) + h * 8;
            if ((lane & 3) == 0 && row < M) atomicAdd(&N2[row], v);
        }
}

// ---------------------------------------------------------------------------
// Fused: s[k] = wa[k]/max(||kt_k||,eps);  v[h] += sum_k s[k]*kt[k][h]
// ---------------------------------------------------------------------------
__global__ __launch_bounds__(256)
void v_accum_kernel(const float* __restrict__ wa_w) {
    __shared__ float se[32];
    const int tid = threadIdx.x;
    const int k0 = blockIdx.x * 32;
    if (tid < 32) {
        int k = k0 + tid;
        se[tid] = (k < NK) ? wa_w[k] / fmaxf(sqrtf(g_kn2[k]), 1e-12f) : 0.f;
    }
    __syncthreads();

    const int c4   = tid & 127;
    const int half = tid >> 7;
    const int r0   = half * 16;
    float4 a0 = make_float4(0.f,0.f,0.f,0.f), a1 = a0, a2 = a0, a3 = a0;
#pragma unroll
    for (int i = 0; i < 16; i += 4) {
        int kA = k0 + r0 + i;
        int kB = kA + 1, kC = kA + 2, kD = kA + 3;
        float sA = se[r0 + i],     sB = se[r0 + i + 1];
        float sC = se[r0 + i + 2], sD = se[r0 + i + 3];
        kA = min(kA, NK - 1); kB = min(kB, NK - 1);
        kC = min(kC, NK - 1); kD = min(kD, NK - 1);
        float4 vA = *(const float4*)(g_kt + (size_t)kA * HD + c4 * 4);
        float4 vB = *(const float4*)(g_kt + (size_t)kB * HD + c4 * 4);
        float4 vC = *(const float4*)(g_kt + (size_t)kC * HD + c4 * 4);
        float4 vD = *(const float4*)(g_kt + (size_t)kD * HD + c4 * 4);
        a0.x = fmaf(sA, vA.x, a0.x); a0.y = fmaf(sA, vA.y, a0.y);
        a0.z = fmaf(sA, vA.z, a0.z); a0.w = fmaf(sA, vA.w, a0.w);
        a1.x = fmaf(sB, vB.x, a1.x); a1.y = fmaf(sB, vB.y, a1.y);
        a1.z = fmaf(sB, vB.z, a1.z); a1.w = fmaf(sB, vB.w, a1.w);
        a2.x = fmaf(sC, vC.x, a2.x); a2.y = fmaf(sC, vC.y, a2.y);
        a2.z = fmaf(sC, vC.z, a2.z); a2.w = fmaf(sC, vC.w, a2.w);
        a3.x = fmaf(sD, vD.x, a3.x); a3.y = fmaf(sD, vD.y, a3.y);
        a3.z = fmaf(sD, vD.z, a3.z); a3.w = fmaf(sD, vD.w, a3.w);
    }
    atomicAdd(&g_v[c4 * 4 + 0], a0.x + a1.x + a2.x + a3.x);
    atomicAdd(&g_v[c4 * 4 + 1], a0.y + a1.y + a2.y + a3.y);
    atomicAdd(&g_v[c4 * 4 + 2], a0.z + a1.z + a2.z + a3.z);
    atomicAdd(&g_v[c4 * 4 + 3], a0.w + a1.w + a2.w + a3.w);
}

// A1[q] = dot(qt_q, v)/max(sqrt(qn2[q]),eps) + wa_b   — 2 rows per warp (MLP=8)
__global__ void a1_kernel(const float* __restrict__ wa_b) {
    int w    = threadIdx.x >> 5;
    int lane = threadIdx.x & 31;
    int row0 = blockIdx.x * 16 + w * 2;
    const float4* q0 = (const float4*)(g_qt + (size_t)row0 * HD);
    const float4* q1 = (const float4*)(g_qt + (size_t)(row0 + 1) * HD);
    const float4* vv = (const float4*)g_v;
    float d0 = 0.f, d1 = 0.f;
#pragma unroll
    for (int j = 0; j < 4; j++) {
        float4 b = vv[lane + 32 * j];
        float4 a = q0[lane + 32 * j];
        float4 c = q1[lane + 32 * j];
        d0 = fmaf(a.x, b.x, fmaf(a.y, b.y, fmaf(a.z, b.z, fmaf(a.w, b.w, d0))));
        d1 = fmaf(c.x, b.x, fmaf(c.y, b.y, fmaf(c.z, b.z, fmaf(c.w, b.w, d1))));
    }
#pragma unroll
    for (int o = 16; o > 0; o >>= 1) {
        d0 += __shfl_xor_sync(0xffffffffu, d0, o);
        d1 += __shfl_xor_sync(0xffffffffu, d1, o);
    }
    if (lane == 0) {
        g_A1[row0]     = d0 / fmaxf(sqrtf(g_qn2[row0]),     1e-12f) + wa_b[0];
        g_A1[row0 + 1] = d1 / fmaxf(sqrtf(g_qn2[row0 + 1]), 1e-12f) + wa_b[0];
    }
}

// ---------------------------------------------------------------------------
// Exact k-th order statistic via 3-level radix select + global max.
// ---------------------------------------------------------------------------
__device__ __forceinline__ uint32_t f2ord(float f) {
    uint32_t u = __float_as_uint(f);
    return u ^ ((u >> 31) ? 0xFFFFFFFFu : 0x80000000u);
}
__device__ __forceinline__ float ord2f(uint32_t u) {
    u ^= ((u >> 31) ? 0x80000000u : 0xFFFFFFFFu);
    return __uint_as_float(u);
}

__global__ void select_kernel() {
    __shared__ uint32_t hist[2048];
    __shared__ uint32_t wred[32];
    __shared__ uint32_t s_bin, s_base;
    __shared__ float s_max;
    const int t = threadIdx.x;
    const int lane = t & 31, w = t >> 5;

    float mx = -INFINITY;
    for (int i = t; i < NQ; i += 1024) mx = fmaxf(mx, g_A1[i]);
#pragma unroll
    for (int o = 16; o > 0; o >>= 1) mx = fmaxf(mx, __shfl_xor_sync(0xffffffffu, mx, o));
    if (lane == 0) wred[w] = __float_as_uint(mx);
    __syncthreads();
    if (w == 0) {
        float m = __uint_as_float(wred[lane]);
#pragma unroll
        for (int o = 16; o > 0; o >>= 1) m = fmaxf(m, __shfl_xor_sync(0xffffffffu, m, o));
        if (lane == 0) s_max = m;
    }
    __syncthreads();

    uint32_t k = THRE_IDX;
    uint32_t prefix = 0, pmask = 0;
    const int shifts[3] = {21, 10, 0};
    const uint32_t widths[3] = {2048, 2048, 1024};

    for (int lev = 0; lev < 3; lev++) {
        const int sh = shifts[lev];
        const uint32_t width = widths[lev];
        const uint32_t bmask = width - 1;
        hist[t] = 0; hist[t + 1024] = 0;
        __syncthreads();
        for (int i = t; i < NQ; i += 1024) {
            uint32_t key = f2ord(g_A1[i]);
            if ((key & pmask) == prefix)
                atomicAdd(&hist[(key >> sh) & bmask], 1u);
        }
        __syncthreads();
        uint32_t c0 = (2u * t     < width) ? hist[2 * t]     : 0u;
        uint32_t c1 = (2u * t + 1 < width) ? hist[2 * t + 1] : 0u;
        uint32_t tsum = c0 + c1;
        uint32_t inc = tsum;
#pragma unroll
        for (int o = 1; o < 32; o <<= 1) {
            uint32_t v = __shfl_up_sync(0xffffffffu, inc, o);
            if (lane >= o) inc += v;
        }
        if (lane == 31) wred[w] = inc;
        __syncthreads();
        if (w == 0) {
            uint32_t v = wred[lane];
            uint32_t winc = v;
#pragma unroll
            for (int o = 1; o < 32; o <<= 1) {
                uint32_t x = __shfl_up_sync(0xffffffffu, winc, o);
                if (lane >= o) winc += x;
            }
            wred[lane] = winc - v;   // exclusive
        }
        __syncthreads();
        uint32_t ex = wred[w] + (inc - tsum);
        if (k >= ex && k < ex + c0)             { s_bin = 2 * t;     s_base = ex; }
        else if (k >= ex + c0 && k < ex + tsum) { s_bin = 2 * t + 1; s_base = ex + c0; }
        __syncthreads();
        uint32_t bin = s_bin;
        k -= s_base;
        prefix |= (bin << sh);
        pmask  |= (bmask << sh);
        __syncthreads();
    }
    if (t == 0) {
        g_thre = ord2f(prefix);
        g_m = fmaxf(s_max, 0.f);
    }
}

// ---------------------------------------------------------------------------
// Fused: e_q = exp(thresholded(A1_q) - m); out[1+q] = e_q; Z += sum e;
//        z[h] += sum_q e_q * qt[q][h]
// ---------------------------------------------------------------------------
__global__ __launch_bounds__(256)
void e_accum_kernel(float* __restrict__ out) {
    __shared__ float se[32];
    const int tid = threadIdx.x;
    const int q0 = blockIdx.x * 32;
    if (tid < 32) {
        int q = q0 + tid;
        float a = g_A1[q];
        float tt = (a > g_thre) ? a : 0.f;
        float e = expf(tt - g_m);
        se[tid] = e;
        out[1 + q] = e;
        float s = e;
#pragma unroll
        for (int o = 16; o > 0; o >>= 1) s += __shfl_xor_sync(0xffffffffu, s, o);
        if (tid == 0) atomicAdd(&g_Z, s);
    }
    __syncthreads();

    const int c4   = tid & 127;
    const int half = tid >> 7;
    const int r0   = half * 16;
    float4 a0 = make_float4(0.f,0.f,0.f,0.f), a1 = a0, a2 = a0, a3 = a0;
#pragma unroll
    for (int i = 0; i < 16; i += 4) {
        int qA = q0 + r0 + i;
        float sA = se[r0 + i],     sB = se[r0 + i + 1];
        float sC = se[r0 + i + 2], sD = se[r0 + i + 3];
        float4 vA = *(const float4*)(g_qt + (size_t)qA * HD + c4 * 4);
        float4 vB = *(const float4*)(g_qt + (size_t)(qA + 1) * HD + c4 * 4);
        float4 vC = *(const float4*)(g_qt + (size_t)(qA + 2) * HD + c4 * 4);
        float4 vD = *(const float4*)(g_qt + (size_t)(qA + 3) * HD + c4 * 4);
        a0.x = fmaf(sA, vA.x, a0.x); a0.y = fmaf(sA, vA.y, a0.y);
        a0.z = fmaf(sA, vA.z, a0.z); a0.w = fmaf(sA, vA.w, a0.w);
        a1.x = fmaf(sB, vB.x, a1.x); a1.y = fmaf(sB, vB.y, a1.y);
        a1.z = fmaf(sB, vB.z, a1.z); a1.w = fmaf(sB, vB.w, a1.w);
        a2.x = fmaf(sC, vC.x, a2.x); a2.y = fmaf(sC, vC.y, a2.y);
        a2.z = fmaf(sC, vC.z, a2.z); a2.w = fmaf(sC, vC.w, a2.w);
        a3.x = fmaf(sD, vD.x, a3.x); a3.y = fmaf(sD, vD.y, a3.y);
        a3.z = fmaf(sD, vD.z, a3.z); a3.w = fmaf(sD, vD.w, a3.w);
    }
    atomicAdd(&g_z[c4 * 4 + 0], a0.x + a1.x + a2.x + a3.x);
    atomicAdd(&g_z[c4 * 4 + 1], a0.y + a1.y + a2.y + a3.y);
    atomicAdd(&g_z[c4 * 4 + 2], a0.z + a1.z + a2.z + a3.z);
    atomicAdd(&g_z[c4 * 4 + 3], a0.w + a1.w + a2.w + a3.w);
}

// ---------------------------------------------------------------------------
__global__ void final_kernel(const float* __restrict__ cls_w,
                             const float* __restrict__ cls_b,
                             float* __restrict__ out) {
    if (blockIdx.x < NQ / 256) {
        int q = blockIdx.x * 256 + threadIdx.x;
        out[1 + q] = out[1 + q] / g_Z;
        return;
    }
    __shared__ float red[16];
    int t = threadIdx.x;
    float p = g_z[t] * cls_w[t] + g_z[t + 256] * cls_w[t + 256];
#pragma unroll
    for (int o = 16; o > 0; o >>= 1) p += __shfl_xor_sync(0xffffffffu, p, o);
    int lane = t & 31, w = t >> 5;
    if (lane == 0) red[w] = p;
    __syncthreads();
    if (w == 0) {
        float s = (lane < 8) ? red[lane] : 0.f;
#pragma unroll
        for (int o = 4; o > 0; o >>= 1) s += __shfl_xor_sync(0xffffffffu, s, o);
        if (lane == 0) out[0] = s / g_Z + cls_b[0];
    }
}

// ---------------------------------------------------------------------------
extern "C" void kernel_launch(void* const* d_in, const int* in_sizes, int n_in,
                              void* d_out, int out_size) {
    const float* query = (const float*)d_in[0];
    const float* key_x = (const float*)d_in[1];
    const float* wq_w  = (const float*)d_in[2];
    const float* wq_b  = (const float*)d_in[3];
    const float* wk_w  = (const float*)d_in[4];
    const float* wk_b  = (const float*)d_in[5];
    const float* wa_w  = (const float*)d_in[6];
    const float* wa_b  = (const float*)d_in[7];
    const float* cls_w = (const float*)d_in[8];
    const float* cls_b = (const float*)d_in[9];
    float* out = (float*)d_out;

    cudaFuncSetAttribute(gemm_tc_kernel,
                         cudaFuncAttributeMaxDynamicSharedMemorySize, GEMM_SMEM);

    init_kernel<<<(NQ + 255) / 256, 256>>>();
    convert_kernel<<<3168, 256>>>(query, key_x, wq_w, wk_w);

    dim3 gg(HD / 128, 128 + NK_PAD / 128);   // (4, 190)
    gemm_tc_kernel<<<gg, 256, GEMM_SMEM>>>(wq_b, wk_b);

    v_accum_kernel<<<(NK + 31) / 32, 256>>>(wa_w);
    a1_kernel<<<NQ / 16, 256>>>(wa_b);
    select_kernel<<<1, 1024>>>();
    e_accum_kernel<<<NQ / 32, 256>>>(out);
    final_kernel<<<NQ / 256 + 1, 256>>>(cls_w, cls_b, out);
}

// round 8
// speedup vs baseline: 1.2929x; 1.2929x over previous
#include <cuda_runtime.h>
#include <cuda_bf16.h>
#include <math.h>
#include <stdint.h>

// Problem constants (fixed shapes from reference)
#define NQ    16384
#define NK    7933
#define D_IN  1024
#define HD    512
#define THRE_IDX 11469   // NQ - int(0.3*NQ)

// ---------------------------------------------------------------------------
// Scratch (device globals)
// ---------------------------------------------------------------------------
__device__ __align__(16) float g_qt[NQ * HD];   // tanh(query @ wq^T)
__device__ __align__(16) float g_kt[NK * HD];   // tanh(key_x @ wk^T)
__device__ float g_qn2[NQ];
__device__ float g_kn2[NK];
__device__ __align__(16) float g_v[HD];
__device__ float g_A1[NQ];
__device__ float g_thre;
__device__ float g_m;
__device__ float g_Z;
__device__ float g_z[HD];

// ---------------------------------------------------------------------------
__global__ void init_kernel() {
    int i = blockIdx.x * 256 + threadIdx.x;
    if (i < NQ) g_qn2[i] = 0.f;
    if (i < NK) g_kn2[i] = 0.f;
    if (i < HD) { g_v[i] = 0.f; g_z[i] = 0.f; }
    if (i == 0) g_Z = 0.f;
}

// ---------------------------------------------------------------------------
// mma.sync bf16 GEMM + tanh + fused row-norm accumulation.  (R4 version)
// hi/lo fp32->bf16 split, 3 products, fp32 accumulate.
// Block 128x128, 8 warps (warp tile 32x64), K-chunk 32 fp32, double-buffered.
// ---------------------------------------------------------------------------
__device__ __forceinline__ uint32_t smem_u32(const void* p) {
    uint32_t a;
    asm("{ .reg .u64 t; cvta.to.shared.u64 t, %1; cvt.u32.u64 %0, t; }" : "=r"(a) : "l"(p));
    return a;
}
__device__ __forceinline__ void ldm_x4(uint32_t* r, uint32_t addr) {
    asm volatile("ldmatrix.sync.aligned.m8n8.x4.shared.b16 {%0,%1,%2,%3}, [%4];"
                 : "=r"(r[0]), "=r"(r[1]), "=r"(r[2]), "=r"(r[3]) : "r"(addr));
}
__device__ __forceinline__ void mma_bf16(float* d, const uint32_t* a, const uint32_t* b) {
    asm volatile(
        "mma.sync.aligned.m16n8k16.row.col.f32.bf16.bf16.f32 "
        "{%0,%1,%2,%3}, {%4,%5,%6,%7}, {%8,%9}, {%0,%1,%2,%3};"
        : "+f"(d[0]), "+f"(d[1]), "+f"(d[2]), "+f"(d[3])
        : "r"(a[0]), "r"(a[1]), "r"(a[2]), "r"(a[3]), "r"(b[0]), "r"(b[1]));
}

#define LDS 40                    // bf16 stride per 32-wide row (+8 pad)
#define NCH (D_IN / 32)           // 32 K-chunks
#define BUF_BYTES 40960
#define GEMM_SMEM (2 * BUF_BYTES) // 81920

__global__ __launch_bounds__(256)
void gemm_tc_kernel(const float* __restrict__ query, const float* __restrict__ wq_w,
                    const float* __restrict__ wq_b,
                    const float* __restrict__ key_x, const float* __restrict__ wk_w,
                    const float* __restrict__ wk_b)
{
    extern __shared__ __align__(16) char sm[];
    const int AH = 0, AL = 10240, WH = 20480, WL = 30720;

    const int tid = threadIdx.x;
    const int wid = tid >> 5;
    const int lane = tid & 31;
    const int by = blockIdx.y;

    const float* Ag; const float* Wg; const float* bias; float* C; float* N2; int M, bm;
    if (by < 128) {
        Ag = query; Wg = wq_w; bias = wq_b; C = g_qt; N2 = g_qn2; M = NQ; bm = by * 128;
    } else {
        Ag = key_x; Wg = wk_w; bias = wk_b; C = g_kt; N2 = g_kn2; M = NK; bm = (by - 128) * 128;
    }
    const int bn = blockIdx.x * 128;

    const uint32_t smb = smem_u32(sm);
    const int warp_m = (wid & 3) * 32;
    const int warp_n = (wid >> 2) * 64;

    float acc[2][8][4];
#pragma unroll
    for (int mt = 0; mt < 2; mt++)
#pragma unroll
        for (int nt = 0; nt < 8; nt++)
#pragma unroll
            for (int i = 0; i < 4; i++) acc[mt][nt][i] = 0.f;

    float4 ra[4], rw[4];
#pragma unroll
    for (int j = 0; j < 4; j++) {
        int idx = tid + j * 256;
        int r = idx >> 3, q = idx & 7;
        int gr = bm + r;
        ra[j] = (gr < M) ? *(const float4*)(Ag + (size_t)gr * D_IN + q * 4)
                         : make_float4(0.f, 0.f, 0.f, 0.f);
        rw[j] = *(const float4*)(Wg + (size_t)(bn + r) * D_IN + q * 4);
    }

    for (int c = 0; c < NCH; c++) {
        const int base = (c & 1) * BUF_BYTES;
#pragma unroll
        for (int j = 0; j < 4; j++) {
            int idx = tid + j * 256;
            int r = idx >> 3, q = idx & 7;
            uint32_t boff = (uint32_t)(r * LDS + q * 4) * 2;
            {
                float4 v = ra[j];
                __nv_bfloat162 h01 = __floats2bfloat162_rn(v.x, v.y);
                __nv_bfloat162 h23 = __floats2bfloat162_rn(v.z, v.w);
                __nv_bfloat162 l01 = __floats2bfloat162_rn(v.x - __bfloat162float(h01.x),
                                                           v.y - __bfloat162float(h01.y));
                __nv_bfloat162 l23 = __floats2bfloat162_rn(v.z - __bfloat162float(h23.x),
                                                           v.w - __bfloat162float(h23.y));
                *(uint2*)(sm + base + AH + boff) = make_uint2(*(uint32_t*)&h01, *(uint32_t*)&h23);
                *(uint2*)(sm + base + AL + boff) = make_uint2(*(uint32_t*)&l01, *(uint32_t*)&l23);
            }
            {
                float4 v = rw[j];
                __nv_bfloat162 h01 = __floats2bfloat162_rn(v.x, v.y);
                __nv_bfloat162 h23 = __floats2bfloat162_rn(v.z, v.w);
                __nv_bfloat162 l01 = __floats2bfloat162_rn(v.x - __bfloat162float(h01.x),
                                                           v.y - __bfloat162float(h01.y));
                __nv_bfloat162 l23 = __floats2bfloat162_rn(v.z - __bfloat162float(h23.x),
                                                           v.w - __bfloat162float(h23.y));
                *(uint2*)(sm + base + WH + boff) = make_uint2(*(uint32_t*)&h01, *(uint32_t*)&h23);
                *(uint2*)(sm + base + WL + boff) = make_uint2(*(uint32_t*)&l01, *(uint32_t*)&l23);
            }
        }
        __syncthreads();

        if (c + 1 < NCH) {
            int k0 = (c + 1) * 32;
#pragma unroll
            for (int j = 0; j < 4; j++) {
                int idx = tid + j * 256;
                int r = idx >> 3, q = idx & 7;
                int gr = bm + r;
                ra[j] = (gr < M) ? *(const float4*)(Ag + (size_t)gr * D_IN + k0 + q * 4)
                                 : make_float4(0.f, 0.f, 0.f, 0.f);
                rw[j] = *(const float4*)(Wg + (size_t)(bn + r) * D_IN + k0 + q * 4);
            }
        }

        const uint32_t sAH = smb + base + AH;
        const uint32_t sAL = smb + base + AL;
        const uint32_t sWH = smb + base + WH;
        const uint32_t sWL = smb + base + WL;
#pragma unroll
        for (int kk = 0; kk < 2; kk++) {
            uint32_t ah[2][4], al[2][4], bh[4][4], bl[4][4];
#pragma unroll
            for (int mt = 0; mt < 2; mt++) {
                int r = warp_m + mt * 16 + (lane & 15);
                int cc = kk * 16 + (lane >> 4) * 8;
                uint32_t off = (uint32_t)(r * LDS + cc) * 2;
                ldm_x4(ah[mt], sAH + off);
                ldm_x4(al[mt], sAL + off);
            }
#pragma unroll
            for (int nt2 = 0; nt2 < 4; nt2++) {
                int r = warp_n + nt2 * 16 + ((lane >> 4) ? 8 : 0) + (lane & 7);
                int cc = kk * 16 + ((lane >> 3) & 1) * 8;
                uint32_t off = (uint32_t)(r * LDS + cc) * 2;
                ldm_x4(bh[nt2], sWH + off);
                ldm_x4(bl[nt2], sWL + off);
            }
#pragma unroll
            for (int mt = 0; mt < 2; mt++)
#pragma unroll
                for (int nt = 0; nt < 8; nt++) {
                    const uint32_t* pbh = &bh[nt >> 1][(nt & 1) * 2];
                    const uint32_t* pbl = &bl[nt >> 1][(nt & 1) * 2];
                    mma_bf16(acc[mt][nt], ah[mt], pbh);
                    mma_bf16(acc[mt][nt], ah[mt], pbl);
                    mma_bf16(acc[mt][nt], al[mt], pbh);
                }
        }
    }

    // ---- epilogue: bias + tanh + fused row-norm partials ----
    float rs[2][2] = {{0.f, 0.f}, {0.f, 0.f}};
#pragma unroll
    for (int mt = 0; mt < 2; mt++) {
        int r0 = bm + warp_m + mt * 16 + (lane >> 2);
#pragma unroll
        for (int nt = 0; nt < 8; nt++) {
            int gc = bn + warp_n + nt * 8 + (lane & 3) * 2;
            float b0 = bias[gc], b1 = bias[gc + 1];
            if (r0 < M) {
                float t0 = tanhf(acc[mt][nt][0] + b0);
                float t1 = tanhf(acc[mt][nt][1] + b1);
                C[(size_t)r0 * HD + gc]     = t0;
                C[(size_t)r0 * HD + gc + 1] = t1;
                rs[mt][0] = fmaf(t0, t0, fmaf(t1, t1, rs[mt][0]));
            }
            if (r0 + 8 < M) {
                float t2 = tanhf(acc[mt][nt][2] + b0);
                float t3 = tanhf(acc[mt][nt][3] + b1);
                C[(size_t)(r0 + 8) * HD + gc]     = t2;
                C[(size_t)(r0 + 8) * HD + gc + 1] = t3;
                rs[mt][1] = fmaf(t2, t2, fmaf(t3, t3, rs[mt][1]));
            }
        }
    }
#pragma unroll
    for (int mt = 0; mt < 2; mt++)
#pragma unroll
        for (int h = 0; h < 2; h++) {
            float v = rs[mt][h];
            v += __shfl_xor_sync(0xffffffffu, v, 1);
            v += __shfl_xor_sync(0xffffffffu, v, 2);
            int row = bm + warp_m + mt * 16 + (lane >> 2) + h * 8;
            if ((lane & 3) == 0 && row < M) atomicAdd(&N2[row], v);
        }
}

// ---------------------------------------------------------------------------
// Fused: s[k] = wa[k]/max(||kt_k||,eps);  v[h] += sum_k s[k]*kt[k][h]
// Grid (ceil(NK/32), 2): 32 rows x 256-float column half per block.
// 4 row-groups x 8 rows/thread (MLP 4), smem pre-reduce, 1 atomic/float/block.
// ---------------------------------------------------------------------------
__global__ __launch_bounds__(256)
void v_accum_kernel(const float* __restrict__ wa_w) {
    __shared__ float se[32];
    __shared__ float sv[256];
    const int tid = threadIdx.x;
    const int k0 = blockIdx.x * 32;
    const int cbase = blockIdx.y * 64;        // float4-column offset of this half
    if (tid < 32) {
        int k = k0 + tid;
        se[tid] = (k < NK) ? wa_w[k] / fmaxf(sqrtf(g_kn2[k]), 1e-12f) : 0.f;
    }
    sv[tid] = 0.f;
    __syncthreads();

    const int c4   = cbase + (tid & 63);
    const int rowg = tid >> 6;                // 0..3
    const int r0   = rowg * 8;
    float4 a0 = make_float4(0.f,0.f,0.f,0.f), a1 = a0, a2 = a0, a3 = a0;
#pragma unroll
    for (int i = 0; i < 8; i += 4) {
        int kA = k0 + r0 + i;
        int kB = kA + 1, kC = kA + 2, kD = kA + 3;
        float sA = se[r0 + i],     sB = se[r0 + i + 1];
        float sC = se[r0 + i + 2], sD = se[r0 + i + 3];
        kA = min(kA, NK - 1); kB = min(kB, NK - 1);
        kC = min(kC, NK - 1); kD = min(kD, NK - 1);
        float4 vA = *(const float4*)(g_kt + (size_t)kA * HD + c4 * 4);
        float4 vB = *(const float4*)(g_kt + (size_t)kB * HD + c4 * 4);
        float4 vC = *(const float4*)(g_kt + (size_t)kC * HD + c4 * 4);
        float4 vD = *(const float4*)(g_kt + (size_t)kD * HD + c4 * 4);
        a0.x = fmaf(sA, vA.x, a0.x); a0.y = fmaf(sA, vA.y, a0.y);
        a0.z = fmaf(sA, vA.z, a0.z); a0.w = fmaf(sA, vA.w, a0.w);
        a1.x = fmaf(sB, vB.x, a1.x); a1.y = fmaf(sB, vB.y, a1.y);
        a1.z = fmaf(sB, vB.z, a1.z); a1.w = fmaf(sB, vB.w, a1.w);
        a2.x = fmaf(sC, vC.x, a2.x); a2.y = fmaf(sC, vC.y, a2.y);
        a2.z = fmaf(sC, vC.z, a2.z); a2.w = fmaf(sC, vC.w, a2.w);
        a3.x = fmaf(sD, vD.x, a3.x); a3.y = fmaf(sD, vD.y, a3.y);
        a3.z = fmaf(sD, vD.z, a3.z); a3.w = fmaf(sD, vD.w, a3.w);
    }
    int lc = (tid & 63) * 4;                  // local float column base
    atomicAdd(&sv[lc + 0], a0.x + a1.x + a2.x + a3.x);
    atomicAdd(&sv[lc + 1], a0.y + a1.y + a2.y + a3.y);
    atomicAdd(&sv[lc + 2], a0.z + a1.z + a2.z + a3.z);
    atomicAdd(&sv[lc + 3], a0.w + a1.w + a2.w + a3.w);
    __syncthreads();
    atomicAdd(&g_v[cbase * 4 + tid], sv[tid]);
}

// A1[q] = dot(qt_q, v)/max(sqrt(qn2[q]),eps) + wa_b   — 2 rows per warp
__global__ void a1_kernel(const float* __restrict__ wa_b) {
    int w    = threadIdx.x >> 5;
    int lane = threadIdx.x & 31;
    int row0 = blockIdx.x * 16 + w * 2;
    const float4* q0 = (const float4*)(g_qt + (size_t)row0 * HD);
    const float4* q1 = (const float4*)(g_qt + (size_t)(row0 + 1) * HD);
    const float4* vv = (const float4*)g_v;
    float d0 = 0.f, d1 = 0.f;
#pragma unroll
    for (int j = 0; j < 4; j++) {
        float4 b = vv[lane + 32 * j];
        float4 a = q0[lane + 32 * j];
        float4 c = q1[lane + 32 * j];
        d0 = fmaf(a.x, b.x, fmaf(a.y, b.y, fmaf(a.z, b.z, fmaf(a.w, b.w, d0))));
        d1 = fmaf(c.x, b.x, fmaf(c.y, b.y, fmaf(c.z, b.z, fmaf(c.w, b.w, d1))));
    }
#pragma unroll
    for (int o = 16; o > 0; o >>= 1) {
        d0 += __shfl_xor_sync(0xffffffffu, d0, o);
        d1 += __shfl_xor_sync(0xffffffffu, d1, o);
    }
    if (lane == 0) {
        g_A1[row0]     = d0 / fmaxf(sqrtf(g_qn2[row0]),     1e-12f) + wa_b[0];
        g_A1[row0 + 1] = d1 / fmaxf(sqrtf(g_qn2[row0 + 1]), 1e-12f) + wa_b[0];
    }
}

// ---------------------------------------------------------------------------
// Exact k-th order statistic via 3-level radix select + global max.
// ---------------------------------------------------------------------------
__device__ __forceinline__ uint32_t f2ord(float f) {
    uint32_t u = __float_as_uint(f);
    return u ^ ((u >> 31) ? 0xFFFFFFFFu : 0x80000000u);
}
__device__ __forceinline__ float ord2f(uint32_t u) {
    u ^= ((u >> 31) ? 0x80000000u : 0xFFFFFFFFu);
    return __uint_as_float(u);
}

__global__ void select_kernel() {
    __shared__ uint32_t hist[2048];
    __shared__ uint32_t wred[32];
    __shared__ uint32_t s_bin, s_base;
    __shared__ float s_max;
    const int t = threadIdx.x;
    const int lane = t & 31, w = t >> 5;

    float mx = -INFINITY;
    for (int i = t; i < NQ; i += 1024) mx = fmaxf(mx, g_A1[i]);
#pragma unroll
    for (int o = 16; o > 0; o >>= 1) mx = fmaxf(mx, __shfl_xor_sync(0xffffffffu, mx, o));
    if (lane == 0) wred[w] = __float_as_uint(mx);
    __syncthreads();
    if (w == 0) {
        float m = __uint_as_float(wred[lane]);
#pragma unroll
        for (int o = 16; o > 0; o >>= 1) m = fmaxf(m, __shfl_xor_sync(0xffffffffu, m, o));
        if (lane == 0) s_max = m;
    }
    __syncthreads();

    uint32_t k = THRE_IDX;
    uint32_t prefix = 0, pmask = 0;
    const int shifts[3] = {21, 10, 0};
    const uint32_t widths[3] = {2048, 2048, 1024};

    for (int lev = 0; lev < 3; lev++) {
        const int sh = shifts[lev];
        const uint32_t width = widths[lev];
        const uint32_t bmask = width - 1;
        hist[t] = 0; hist[t + 1024] = 0;
        __syncthreads();
        for (int i = t; i < NQ; i += 1024) {
            uint32_t key = f2ord(g_A1[i]);
            if ((key & pmask) == prefix)
                atomicAdd(&hist[(key >> sh) & bmask], 1u);
        }
        __syncthreads();
        uint32_t c0 = (2u * t     < width) ? hist[2 * t]     : 0u;
        uint32_t c1 = (2u * t + 1 < width) ? hist[2 * t + 1] : 0u;
        uint32_t tsum = c0 + c1;
        uint32_t inc = tsum;
#pragma unroll
        for (int o = 1; o < 32; o <<= 1) {
            uint32_t v = __shfl_up_sync(0xffffffffu, inc, o);
            if (lane >= o) inc += v;
        }
        if (lane == 31) wred[w] = inc;
        __syncthreads();
        if (w == 0) {
            uint32_t v = wred[lane];
            uint32_t winc = v;
#pragma unroll
            for (int o = 1; o < 32; o <<= 1) {
                uint32_t x = __shfl_up_sync(0xffffffffu, winc, o);
                if (lane >= o) winc += x;
            }
            wred[lane] = winc - v;   // exclusive
        }
        __syncthreads();
        uint32_t ex = wred[w] + (inc - tsum);
        if (k >= ex && k < ex + c0)             { s_bin = 2 * t;     s_base = ex; }
        else if (k >= ex + c0 && k < ex + tsum) { s_bin = 2 * t + 1; s_base = ex + c0; }
        __syncthreads();
        uint32_t bin = s_bin;
        k -= s_base;
        prefix |= (bin << sh);
        pmask  |= (bmask << sh);
        __syncthreads();
    }
    if (t == 0) {
        g_thre = ord2f(prefix);
        g_m = fmaxf(s_max, 0.f);
    }
}

// ---------------------------------------------------------------------------
// Fused: e_q = exp(thresholded(A1_q) - m); out[1+q] = e_q; Z += sum e;
//        z[h] += sum_q e_q * qt[q][h]
// Grid (NQ/32, 2): 32 rows x 256-float column half; smem pre-reduce.
// ---------------------------------------------------------------------------
__global__ __launch_bounds__(256)
void e_accum_kernel(float* __restrict__ out) {
    __shared__ float se[32];
    __shared__ float sz[256];
    const int tid = threadIdx.x;
    const int q0 = blockIdx.x * 32;
    const int cbase = blockIdx.y * 64;
    if (tid < 32) {
        int q = q0 + tid;
        float a = g_A1[q];
        float tt = (a > g_thre) ? a : 0.f;
        float e = expf(tt - g_m);
        se[tid] = e;
        if (blockIdx.y == 0) {
            out[1 + q] = e;
            float s = e;
#pragma unroll
            for (int o = 16; o > 0; o >>= 1) s += __shfl_xor_sync(0xffffffffu, s, o);
            if (tid == 0) atomicAdd(&g_Z, s);
        }
    }
    sz[tid] = 0.f;
    __syncthreads();

    const int c4   = cbase + (tid & 63);
    const int rowg = tid >> 6;
    const int r0   = rowg * 8;
    float4 a0 = make_float4(0.f,0.f,0.f,0.f), a1 = a0, a2 = a0, a3 = a0;
#pragma unroll
    for (int i = 0; i < 8; i += 4) {
        int qA = q0 + r0 + i;
        float sA = se[r0 + i],     sB = se[r0 + i + 1];
        float sC = se[r0 + i + 2], sD = se[r0 + i + 3];
        float4 vA = *(const float4*)(g_qt + (size_t)qA * HD + c4 * 4);
        float4 vB = *(const float4*)(g_qt + (size_t)(qA + 1) * HD + c4 * 4);
        float4 vC = *(const float4*)(g_qt + (size_t)(qA + 2) * HD + c4 * 4);
        float4 vD = *(const float4*)(g_qt + (size_t)(qA + 3) * HD + c4 * 4);
        a0.x = fmaf(sA, vA.x, a0.x); a0.y = fmaf(sA, vA.y, a0.y);
        a0.z = fmaf(sA, vA.z, a0.z); a0.w = fmaf(sA, vA.w, a0.w);
        a1.x = fmaf(sB, vB.x, a1.x); a1.y = fmaf(sB, vB.y, a1.y);
        a1.z = fmaf(sB, vB.z, a1.z); a1.w = fmaf(sB, vB.w, a1.w);
        a2.x = fmaf(sC, vC.x, a2.x); a2.y = fmaf(sC, vC.y, a2.y);
        a2.z = fmaf(sC, vC.z, a2.z); a2.w = fmaf(sC, vC.w, a2.w);
        a3.x = fmaf(sD, vD.x, a3.x); a3.y = fmaf(sD, vD.y, a3.y);
        a3.z = fmaf(sD, vD.z, a3.z); a3.w = fmaf(sD, vD.w, a3.w);
    }
    int lc = (tid & 63) * 4;
    atomicAdd(&sz[lc + 0], a0.x + a1.x + a2.x + a3.x);
    atomicAdd(&sz[lc + 1], a0.y + a1.y + a2.y + a3.y);
    atomicAdd(&sz[lc + 2], a0.z + a1.z + a2.z + a3.z);
    atomicAdd(&sz[lc + 3], a0.w + a1.w + a2.w + a3.w);
    __syncthreads();
    atomicAdd(&g_z[cbase * 4 + tid], sz[tid]);
}

// ---------------------------------------------------------------------------
__global__ void final_kernel(const float* __restrict__ cls_w,
                             const float* __restrict__ cls_b,
                             float* __restrict__ out) {
    if (blockIdx.x < NQ / 256) {
        int q = blockIdx.x * 256 + threadIdx.x;
        out[1 + q] = out[1 + q] / g_Z;
        return;
    }
    __shared__ float red[16];
    int t = threadIdx.x;
    float p = g_z[t] * cls_w[t] + g_z[t + 256] * cls_w[t + 256];
#pragma unroll
    for (int o = 16; o > 0; o >>= 1) p += __shfl_xor_sync(0xffffffffu, p, o);
    int lane = t & 31, w = t >> 5;
    if (lane == 0) red[w] = p;
    __syncthreads();
    if (w == 0) {
        float s = (lane < 8) ? red[lane] : 0.f;
#pragma unroll
        for (int o = 4; o > 0; o >>= 1) s += __shfl_xor_sync(0xffffffffu, s, o);
        if (lane == 0) out[0] = s / g_Z + cls_b[0];
    }
}

// ---------------------------------------------------------------------------
extern "C" void kernel_launch(void* const* d_in, const int* in_sizes, int n_in,
                              void* d_out, int out_size) {
    const float* query = (const float*)d_in[0];
    const float* key_x = (const float*)d_in[1];
    const float* wq_w  = (const float*)d_in[2];
    const float* wq_b  = (const float*)d_in[3];
    const float* wk_w  = (const float*)d_in[4];
    const float* wk_b  = (const float*)d_in[5];
    const float* wa_w  = (const float*)d_in[6];
    const float* wa_b  = (const float*)d_in[7];
    const float* cls_w = (const float*)d_in[8];
    const float* cls_b = (const float*)d_in[9];
    float* out = (float*)d_out;

    cudaFuncSetAttribute(gemm_tc_kernel,
                         cudaFuncAttributeMaxDynamicSharedMemorySize, GEMM_SMEM);

    init_kernel<<<(NQ + 255) / 256, 256>>>();

    dim3 gg(HD / 128, 128 + (NK + 127) / 128);
    gemm_tc_kernel<<<gg, 256, GEMM_SMEM>>>(query, wq_w, wq_b, key_x, wk_w, wk_b);

    v_accum_kernel<<<dim3((NK + 31) / 32, 2), 256>>>(wa_w);
    a1_kernel<<<NQ / 16, 256>>>(wa_b);
    select_kernel<<<1, 1024>>>();
    e_accum_kernel<<<dim3(NQ / 32, 2), 256>>>(out);
    final_kernel<<<NQ / 256 + 1, 256>>>(cls_w, cls_b, out);
}